// round 13
// baseline (speedup 1.0000x reference)
#include <cuda_runtime.h>
#include <cuda_bf16.h>

// Fused SSIM, R8: R4 algorithm (4 conv quantities (a,c,ac,a^2+c^2) in float4,
// even/odd deinterleaved smem rows, 2 px/thread, register vertical scatter
// ring) with: 128-reg cap (4 CTAs/SM, 16 warps), balanced 576-CTA single
// wave (6 y-bands, two template heights), 4-row stages (8-slot ring, half the
// barriers), LDG.64 pair loads, multiply-overwrite ring recycling, in-kernel
// ticket reduction.

#define IMG_W 512
#define IMG_H 512
#define PLANE_STRIDE (512*512)
#define NTHR 128
#define NBLOCKS 576          // 48 planes * 2 x-strips * 6 y-bands
#define C1_CONST 0.0001f
#define C2_CONST 0.0009f

#define W0 0.00102838f
#define W1 0.00759876f
#define W2 0.03600077f
#define W3 0.10936080f
#define W4 0.21300555f
#define W5 0.26601174f

__device__ float    g_partial[NBLOCKS];
__device__ unsigned g_cnt = 0;

__device__ __forceinline__ float gwt(int k) {
    switch (k) {
        case 0: case 10: return W0;
        case 1: case 9:  return W1;
        case 2: case 8:  return W2;
        case 3: case 7:  return W3;
        case 4: case 6:  return W4;
        default:         return W5;
    }
}

__device__ __forceinline__ void f4fma(float4 &a, const float4 v, const float w) {
    a.x = fmaf(v.x, w, a.x);
    a.y = fmaf(v.y, w, a.y);
    a.z = fmaf(v.z, w, a.z);
    a.w = fmaf(v.w, w, a.w);
}
__device__ __forceinline__ float4 f4scale(const float4 v, const float w) {
    return make_float4(v.x * w, v.y * w, v.z * w, v.w * w);
}

// One band: NSTEPS_T input rows (H = NSTEPS_T-10 output rows), NSTAGES_T = NSTEPS_T/4.
template<int NSTEPS_T, int NSTAGES_T>
__device__ __forceinline__ float band_loop(
    const float* __restrict__ p1, const float* __restrict__ p2,
    const int x0, const int y0, const int t,
    float4 (* __restrict__ Ev)[136], float4 (* __restrict__ Od)[136])
{
    float4 accA[11], accB[11];
#pragma unroll
    for (int j = 0; j < 11; ++j) {
        accA[j] = make_float4(0.f, 0.f, 0.f, 0.f);
        accB[j] = make_float4(0.f, 0.f, 0.f, 0.f);
    }
    float lsum = 0.f;

    auto load_row = [&](int step) {
        if (step >= NSTEPS_T) return;            // uniform; slot never read
        const int  slot = step & 7;
        const int  r    = y0 - 5 + step;
        const bool rok  = ((unsigned)r < (unsigned)IMG_H);
        const float* q1 = p1 + (size_t)(rok ? r : 0) * IMG_W;
        const float* q2 = p2 + (size_t)(rok ? r : 0) * IMG_W;
        {
            const int  gx = x0 - 6 + 2 * t;      // even; pair (gx, gx+1) uniform in/out
            const bool ok = rok && ((unsigned)gx < (unsigned)IMG_W);
            const float2 A = ok ? __ldg((const float2*)(q1 + gx)) : make_float2(0.f, 0.f);
            const float2 C = ok ? __ldg((const float2*)(q2 + gx)) : make_float2(0.f, 0.f);
            Ev[slot][t] = make_float4(A.x, C.x, A.x * C.x, fmaf(A.x, A.x, C.x * C.x));
            Od[slot][t] = make_float4(A.y, C.y, A.y * C.y, fmaf(A.y, A.y, C.y * C.y));
        }
        if (t < 6) {                              // tail px 250..261 (rel); pairs uniform
            const int  g2 = x0 + 250 + 2 * t;
            const bool ok = rok && (g2 < IMG_W);
            const float2 A = ok ? __ldg((const float2*)(q1 + g2)) : make_float2(0.f, 0.f);
            const float2 C = ok ? __ldg((const float2*)(q2 + g2)) : make_float2(0.f, 0.f);
            Ev[slot][128 + t] = make_float4(A.x, C.x, A.x * C.x, fmaf(A.x, A.x, C.x * C.x));
            Od[slot][128 + t] = make_float4(A.y, C.y, A.y * C.y, fmaf(A.y, A.y, C.y * C.y));
        }
    };

    auto epi = [&](const float4 q) {   // q = (mu1, mu2, e12, e11+e22)
        const float m11 = q.x * q.x;
        const float m22 = q.y * q.y;
        const float m12 = q.x * q.y;
        const float num = (2.f * m12 + C1_CONST) * (2.f * (q.z - m12) + C2_CONST);
        const float den = (m11 + m22 + C1_CONST) * ((q.w - m11 - m22) + C2_CONST);
        lsum += __fdividef(num, den);
    };

#define PROC(SV, RR) {                                                         \
    const int sl_ = (SV) & 7;                                                  \
    const float4* ev = Ev[sl_];                                                \
    const float4* od = Od[sl_];                                                \
    float4 hA = make_float4(0.f, 0.f, 0.f, 0.f);                               \
    float4 hB = make_float4(0.f, 0.f, 0.f, 0.f);                               \
    float4 v_;                                                                 \
    v_ = od[t];     f4fma(hA, v_, W0);                                         \
    v_ = ev[t + 1]; f4fma(hA, v_, W1); f4fma(hB, v_, W0);                      \
    v_ = od[t + 1]; f4fma(hA, v_, W2); f4fma(hB, v_, W1);                      \
    v_ = ev[t + 2]; f4fma(hA, v_, W3); f4fma(hB, v_, W2);                      \
    v_ = od[t + 2]; f4fma(hA, v_, W4); f4fma(hB, v_, W3);                      \
    v_ = ev[t + 3]; f4fma(hA, v_, W5); f4fma(hB, v_, W4);                      \
    v_ = od[t + 3]; f4fma(hA, v_, W4); f4fma(hB, v_, W5);                      \
    v_ = ev[t + 4]; f4fma(hA, v_, W3); f4fma(hB, v_, W4);                      \
    v_ = od[t + 4]; f4fma(hA, v_, W2); f4fma(hB, v_, W3);                      \
    v_ = ev[t + 5]; f4fma(hA, v_, W1); f4fma(hB, v_, W2);                      \
    v_ = od[t + 5]; f4fma(hA, v_, W0); f4fma(hB, v_, W1);                      \
    v_ = ev[t + 6];                    f4fma(hB, v_, W0);                      \
    _Pragma("unroll")                                                          \
    for (int j = 0; j < 10; ++j) {                                             \
        const float wj = gwt(j);                                               \
        const int sl = ((RR) + j) % 11;                                        \
        f4fma(accA[sl], hA, wj);                                               \
        f4fma(accB[sl], hB, wj);                                               \
    }                                                                          \
    {   /* j=10: first tap of freshly recycled slot -> overwrite */            \
        const int sl = ((RR) + 10) % 11;                                       \
        accA[sl] = f4scale(hA, W0);                                            \
        accB[sl] = f4scale(hB, W0);                                            \
    }                                                                          \
    if ((SV) >= 10) { epi(accA[RR]); epi(accB[RR]); }                          \
}

    // prologue: rows 0..3 into slots 0..3
    load_row(0); load_row(1); load_row(2); load_row(3);
    __syncthreads();

    int s = 0;
#pragma unroll 1
    for (int blk = 0; blk < 2; ++blk) {          // 2 * 11 stages * 4 rows = 88 rows
#pragma unroll
        for (int it = 0; it < 11; ++it) {        // s % 11 == (4*it) % 11
            load_row(s + 4); load_row(s + 5); load_row(s + 6); load_row(s + 7);
            PROC(s,     (4 * it)     % 11);
            PROC(s + 1, (4 * it + 1) % 11);
            PROC(s + 2, (4 * it + 2) % 11);
            PROC(s + 3, (4 * it + 3) % 11);
            __syncthreads();
            s += 4;
        }
    }
#pragma unroll
    for (int it = 0; it < NSTAGES_T - 22; ++it) { // rows 88.. (88 % 11 == 0)
        load_row(s + 4); load_row(s + 5); load_row(s + 6); load_row(s + 7);
        PROC(s,     (4 * it)     % 11);
        PROC(s + 1, (4 * it + 1) % 11);
        PROC(s + 2, (4 * it + 2) % 11);
        PROC(s + 3, (4 * it + 3) % 11);
        __syncthreads();
        s += 4;
    }
#undef PROC
    return lsum;
}

__global__ void __launch_bounds__(NTHR, 4)
ssim_kernel(const float* __restrict__ img1, const float* __restrict__ img2,
            float* __restrict__ out) {
    __shared__ float4 Ev[8][136];
    __shared__ float4 Od[8][136];
    __shared__ float  wsum[4];
    __shared__ int    s_last;

    const int t = threadIdx.x;
    const int b = blockIdx.x;
    const int plane = b / 12;
    const int rem   = b % 12;
    const int x0 = (rem & 1) * 256;
    const int yb = rem >> 1;             // 0..5
    const int y0 = yb * 86;              // heights: 86,86,86,86,86,82

    const float* p1 = img1 + (size_t)plane * PLANE_STRIDE;
    const float* p2 = img2 + (size_t)plane * PLANE_STRIDE;

    // bands 0..4: H=86 -> 96 steps / 24 stages; band 5: H=82 -> 92 / 23
    const float lsum = (yb < 5)
        ? band_loop<96, 24>(p1, p2, x0, y0, t, Ev, Od)
        : band_loop<92, 23>(p1, p2, x0, y0, t, Ev, Od);

    // deterministic per-CTA partial (4 warps)
    float v = lsum;
#pragma unroll
    for (int o = 16; o; o >>= 1) v += __shfl_xor_sync(0xffffffffu, v, o);
    if ((t & 31) == 0) wsum[t >> 5] = v;
    __syncthreads();
    if (t == 0) {
        g_partial[b] = (wsum[0] + wsum[1]) + (wsum[2] + wsum[3]);
        __threadfence();
        const unsigned tk = atomicInc(&g_cnt, NBLOCKS - 1);  // self-resetting
        s_last = (tk == NBLOCKS - 1);
    }
    __syncthreads();

    // last CTA: deterministic final reduction over 576 partials
    if (s_last) {
        float sv = __ldcg(&g_partial[t])       + __ldcg(&g_partial[t + 128]) +
                   __ldcg(&g_partial[t + 256]) + __ldcg(&g_partial[t + 384]) +
                   ((t < 64) ? __ldcg(&g_partial[t + 512]) : 0.f);
#pragma unroll
        for (int o = 16; o; o >>= 1) sv += __shfl_xor_sync(0xffffffffu, sv, o);
        if ((t & 31) == 0) wsum[t >> 5] = sv;
        __syncthreads();
        if (t == 0) {
            out[0] = ((wsum[0] + wsum[1]) + (wsum[2] + wsum[3])) *
                     (1.0f / 12582912.0f);
        }
    }
}

extern "C" void kernel_launch(void* const* d_in, const int* in_sizes, int n_in,
                              void* d_out, int out_size) {
    const float* img1 = (const float*)d_in[0];
    const float* img2 = (const float*)d_in[1];
    (void)in_sizes; (void)n_in; (void)out_size;
    ssim_kernel<<<NBLOCKS, NTHR>>>(img1, img2, (float*)d_out);
}